// round 1
// baseline (speedup 1.0000x reference)
#include <cuda_runtime.h>

// out[N] = inputs[N, 272] @ weights[272] + bias
// weights[0:16]   = kernel
// weights[16:272] = kernel[i0]*kernel[i3]*w1 + kernel[i1]*kernel[i2]*w2
//   for pair index p: x1=p/16, x2=p%16; a1=x1/4,b1=x1%4,a2=x2/4,b2=x2%4
//   i0=4a1+a2, i1=4a1+b2, i2=4b1+a2, i3=4b1+b2
//
// Strategy: pure HBM-streaming GEMV. Warp per row, float4 coalesced loads,
// weights rebuilt per block in shared memory (cost: ~20 L2-cached reads).

#define UNITS 16
#define DIM   272
#define DIM4  68          // 272 / 4
#define WARPS_PER_BLOCK 8
#define BLOCK_THREADS   256

__global__ void __launch_bounds__(BLOCK_THREADS)
linear_gemv_kernel(const float* __restrict__ inputs,
                   const float* __restrict__ kernel,
                   const float* __restrict__ w1,
                   const float* __restrict__ w2,
                   const float* __restrict__ bias,
                   float* __restrict__ out,
                   int n)
{
    __shared__ float4 w4[DIM4];
    __shared__ float  sk[UNITS];

    const int tid = threadIdx.x;

    // Stage the 16 kernel values once.
    if (tid < UNITS) sk[tid] = kernel[tid];
    __syncthreads();

    // Build the full 272-element weight vector in shared memory.
    float* w = reinterpret_cast<float*>(w4);
    if (tid < UNITS) w[tid] = sk[tid];
    {
        // one pair weight per thread (256 threads, 256 pairs)
        const int x1 = tid >> 4;
        const int x2 = tid & 15;
        const int a1 = x1 >> 2, b1 = x1 & 3;
        const int a2 = x2 >> 2, b2 = x2 & 3;
        const float pw = sk[4 * a1 + a2] * sk[4 * b1 + b2] * w1[0]
                       + sk[4 * a1 + b2] * sk[4 * b1 + a2] * w2[0];
        w[UNITS + tid] = pw;
    }
    __syncthreads();

    const float bv = bias[0];

    const int warp = tid >> 5;
    const int lane = tid & 31;
    const int row  = blockIdx.x * WARPS_PER_BLOCK + warp;
    if (row >= n) return;

    const float4* __restrict__ in =
        reinterpret_cast<const float4*>(inputs + (size_t)row * DIM);

    float acc = 0.0f;

    // 68 float4 per row: lanes cover j = lane, lane+32, lane+64 (lane<4)
    {
        const float4 a = in[lane];
        const float4 b = w4[lane];
        acc = fmaf(a.x, b.x, fmaf(a.y, b.y, fmaf(a.z, b.z, a.w * b.w)));
    }
    {
        const float4 a = in[lane + 32];
        const float4 b = w4[lane + 32];
        acc += fmaf(a.x, b.x, fmaf(a.y, b.y, fmaf(a.z, b.z, a.w * b.w)));
    }
    if (lane < 4) {
        const float4 a = in[lane + 64];
        const float4 b = w4[lane + 64];
        acc += fmaf(a.x, b.x, fmaf(a.y, b.y, fmaf(a.z, b.z, a.w * b.w)));
    }

    // warp reduction
    #pragma unroll
    for (int off = 16; off > 0; off >>= 1)
        acc += __shfl_down_sync(0xffffffffu, acc, off);

    if (lane == 0) out[row] = acc + bv;
}

extern "C" void kernel_launch(void* const* d_in, const int* in_sizes, int n_in,
                              void* d_out, int out_size)
{
    const float* inputs = (const float*)d_in[0];
    const float* kernel = (const float*)d_in[1];
    const float* w1     = (const float*)d_in[2];
    const float* w2     = (const float*)d_in[3];
    const float* bias   = (const float*)d_in[4];
    float* out = (float*)d_out;

    const int n = out_size;  // number of rows
    const int blocks = (n + WARPS_PER_BLOCK - 1) / WARPS_PER_BLOCK;
    linear_gemv_kernel<<<blocks, BLOCK_THREADS>>>(inputs, kernel, w1, w2, bias, out, n);
}

// round 2
// speedup vs baseline: 1.0882x; 1.0882x over previous
#include <cuda_runtime.h>

// out[N] = inputs[N, 272] @ weights[272] + bias
// weights[0:16]   = kernel
// weights[16:272] = kernel[i0]*kernel[i3]*w1 + kernel[i1]*kernel[i2]*w2
//
// Strategy: HBM-streaming GEMV, 2 rows per warp so each warp's footprint is
// exactly 17 cache lines (2176 B, 128B-aligned). All loads line-aligned:
// 4 full-warp 512B float4 loads + one 8-lane 128B tail. Streaming (__ldcs).

#define UNITS 16
#define DIM   272
#define DIM4  68          // 272 / 4
#define PAIR4 136         // 2 rows in float4 units
#define WARPS_PER_BLOCK 8
#define BLOCK_THREADS   256
#define FULLMASK 0xffffffffu

__device__ __forceinline__ float dot4(float4 a, float4 b) {
    return fmaf(a.x, b.x, fmaf(a.y, b.y, fmaf(a.z, b.z, a.w * b.w)));
}

__global__ void __launch_bounds__(BLOCK_THREADS)
linear_gemv_kernel(const float* __restrict__ inputs,
                   const float* __restrict__ kernel,
                   const float* __restrict__ w1,
                   const float* __restrict__ w2,
                   const float* __restrict__ bias,
                   float* __restrict__ out,
                   int n)
{
    __shared__ float4 w4[DIM4];
    __shared__ float  sk[UNITS];

    const int tid = threadIdx.x;

    // Stage the 16 kernel values once.
    if (tid < UNITS) sk[tid] = kernel[tid];
    __syncthreads();

    // Build the 272-element weight vector in shared memory.
    float* w = reinterpret_cast<float*>(w4);
    if (tid < UNITS) w[tid] = sk[tid];
    {
        // one pair weight per thread (256 threads, 256 pairs)
        const int x1 = tid >> 4;
        const int x2 = tid & 15;
        const int a1 = x1 >> 2, b1 = x1 & 3;
        const int a2 = x2 >> 2, b2 = x2 & 3;
        const float pw = sk[4 * a1 + a2] * sk[4 * b1 + b2] * w1[0]
                       + sk[4 * a1 + b2] * sk[4 * b1 + a2] * w2[0];
        w[UNITS + tid] = pw;
    }
    __syncthreads();

    const float bv = bias[0];

    const int warp = tid >> 5;
    const int lane = tid & 31;
    const int pair = blockIdx.x * WARPS_PER_BLOCK + warp;  // 2-row group index
    const int r0   = pair * 2;
    if (r0 >= n) return;

    const float4* __restrict__ in =
        reinterpret_cast<const float4*>(inputs) + (size_t)pair * PAIR4;

    // Issue all loads up front for max MLP. All line-aligned.
    const float4 a0 = __ldcs(in + lane);         // j in [0,32)    -> row0
    const float4 a1 = __ldcs(in + lane + 32);    // j in [32,64)   -> row0
    const float4 a2 = __ldcs(in + lane + 64);    // j in [64,96)   -> row0 if lane<4
    const float4 a3 = __ldcs(in + lane + 96);    // j in [96,128)  -> row1
    float4 a4 = make_float4(0.f, 0.f, 0.f, 0.f);
    if (lane < 8) a4 = __ldcs(in + lane + 128);  // j in [128,136) -> row1

    float acc0 = dot4(a0, w4[lane]);
    acc0 += dot4(a1, w4[lane + 32]);

    // j = lane+64: row0 col (lane+64) if lane<4, else row1 col (lane-4)
    const int wi2 = (lane < 4) ? (lane + 64) : (lane - 4);
    const float d2 = dot4(a2, w4[wi2]);
    float acc1 = (lane < 4) ? 0.0f : d2;
    if (lane < 4) acc0 += d2;

    acc1 += dot4(a3, w4[lane + 28]);             // col = lane+96-68
    if (lane < 8) acc1 += dot4(a4, w4[lane + 60]); // col = lane+128-68

    // Paired reduction: fold both accumulators across half-warps, then
    // reduce one value per 16-lane group. lane0 -> row0, lane16 -> row1.
    acc0 += __shfl_xor_sync(FULLMASK, acc0, 16);
    acc1 += __shfl_xor_sync(FULLMASK, acc1, 16);
    float v = (lane & 16) ? acc1 : acc0;
    v += __shfl_xor_sync(FULLMASK, v, 8);
    v += __shfl_xor_sync(FULLMASK, v, 4);
    v += __shfl_xor_sync(FULLMASK, v, 2);
    v += __shfl_xor_sync(FULLMASK, v, 1);

    if (lane == 0)                    out[r0]     = v + bv;
    if (lane == 16 && (r0 + 1) < n)   out[r0 + 1] = v + bv;
}

extern "C" void kernel_launch(void* const* d_in, const int* in_sizes, int n_in,
                              void* d_out, int out_size)
{
    const float* inputs = (const float*)d_in[0];
    const float* kernel = (const float*)d_in[1];
    const float* w1     = (const float*)d_in[2];
    const float* w2     = (const float*)d_in[3];
    const float* bias   = (const float*)d_in[4];
    float* out = (float*)d_out;

    const int n = out_size;  // number of rows
    const int pairs = (n + 1) / 2;
    const int blocks = (pairs + WARPS_PER_BLOCK - 1) / WARPS_PER_BLOCK;
    linear_gemv_kernel<<<blocks, BLOCK_THREADS>>>(inputs, kernel, w1, w2, bias, out, n);
}